// round 4
// baseline (speedup 1.0000x reference)
#include <cuda_runtime.h>
#include <math.h>

// StateCompressor: VQ-VAE style encode -> quantize -> decode.
// Shapes: B=8,N=2048 -> M=16384 tokens; D=4096, H=2048, C=512, K=1024 codes.
//
// Output layout (float32, concatenated in reference-return order):
//   reconstructed [16384*4096] | compressed [16384*512] | quantized [16384*512]
//   | indices-as-float [16384] | commitment_loss [1] | reconstruction_loss [1]
//
// Round 4: B-fragment remapped from 8 contiguous cols (tx*8, 2-way LDS bank
// conflict: bank-quads {0,2,4,6,0,2,4,6} per phase) to split 4+4 cols at
// tx*4 and 64+tx*4 (bank-quads {0..7}, conflict-free). Brings smem cycles
// per 128x128x16 tile from 3072 down to the 2048-cycle FFMA floor.
// Argmin path stays fully fp32 (one flipped index ~= 1% rel error).

#define M_TOK 16384
#define D_DIM 4096
#define H_DIM 2048
#define C_DIM 512
#define K_CB  1024

#define OFF_RECON 0ull
#define OFF_COMP  67108864ull
#define OFF_QUANT 75497472ull
#define OFF_IDX   83886080ull
#define OFF_CLOSS 83902464ull
#define OFF_RLOSS 83902465ull

__device__ __align__(16) float g_h[(size_t)M_TOK * H_DIM];   // 128 MiB scratch (reused)
__device__ float  g_cn[K_CB];
__device__ int    g_idx[M_TOK];
__device__ float  g_comm_tok[M_TOK];
__device__ double g_partial[2048];

__device__ __forceinline__ float gelu_exact(float v)
{
    return 0.5f * v * (1.0f + erff(v * 0.70710678118654752f));
}

// ---------------------------------------------------------------------------
// Generic NT GEMM: C[m,n] = sum_k A[m,k]*B[n,k] + bias[n], optional exact GELU.
// A: MxK row-major. B: NxK row-major (torch Linear weight). C: MxN row-major.
// 128x128 tile, BK=16, double-buffered smem (one __syncthreads per K-tile).
// Per-thread tile: 8 rows (ty*8, contiguous) x (4 cols @ tx*4 + 4 cols @
// 64+tx*4). B-fragment LDS.128s are conflict-free in this layout.
// Requires M%128==0, N%128==0, K%32==0 (true for all call sites).
// ---------------------------------------------------------------------------
template<bool GELU>
__global__ __launch_bounds__(256)
void gemm_nt_bias(const float* __restrict__ A, const float* __restrict__ B,
                  const float* __restrict__ bias, float* __restrict__ C,
                  int M, int N, int K)
{
    const int BK = 16;
    __shared__ float As[2][16][132];
    __shared__ float Bs[2][16][132];

    const int bm = blockIdx.y * 128;
    const int bn = blockIdx.x * 128;
    const int tid = threadIdx.x;
    const int tx = tid & 15;        // 0..15 -> cols tx*4..tx*4+3 and 64+tx*4..
    const int ty = tid >> 4;        // 0..15 -> rows ty*8..ty*8+7
    const int lr = tid >> 2;        // 0..63 load row
    const int lc = (tid & 3) << 2;  // 0,4,8,12 load col (float4)

    const float* Ap0 = A + (size_t)(bm + lr)      * K + lc;
    const float* Ap1 = A + (size_t)(bm + lr + 64) * K + lc;
    const float* Bp0 = B + (size_t)(bn + lr)      * K + lc;
    const float* Bp1 = B + (size_t)(bn + lr + 64) * K + lc;

    // acc[i][j]: j 0..3 -> col tx*4+j ; j 4..7 -> col 64+tx*4+(j-4)
    float acc[8][8];
    #pragma unroll
    for (int i = 0; i < 8; ++i)
        #pragma unroll
        for (int j = 0; j < 8; ++j) acc[i][j] = 0.f;

    // Preload tile 0 into buffer 0.
    {
        float4 pa0 = *(const float4*)(Ap0);
        float4 pb0 = *(const float4*)(Bp0);
        float4 pa1 = *(const float4*)(Ap1);
        float4 pb1 = *(const float4*)(Bp1);
        As[0][lc+0][lr]    = pa0.x; As[0][lc+1][lr]    = pa0.y; As[0][lc+2][lr]    = pa0.z; As[0][lc+3][lr]    = pa0.w;
        Bs[0][lc+0][lr]    = pb0.x; Bs[0][lc+1][lr]    = pb0.y; Bs[0][lc+2][lr]    = pb0.z; Bs[0][lc+3][lr]    = pb0.w;
        As[0][lc+0][lr+64] = pa1.x; As[0][lc+1][lr+64] = pa1.y; As[0][lc+2][lr+64] = pa1.z; As[0][lc+3][lr+64] = pa1.w;
        Bs[0][lc+0][lr+64] = pb1.x; Bs[0][lc+1][lr+64] = pb1.y; Bs[0][lc+2][lr+64] = pb1.z; Bs[0][lc+3][lr+64] = pb1.w;
    }
    __syncthreads();

    for (int kt = 0; kt < K; kt += BK) {
        const int cur = (kt >> 4) & 1;
        const bool more = (kt + BK) < K;

        float4 pa0, pa1, pb0, pb1;
        if (more) {
            pa0 = *(const float4*)(Ap0 + kt + BK);
            pb0 = *(const float4*)(Bp0 + kt + BK);
            pa1 = *(const float4*)(Ap1 + kt + BK);
            pb1 = *(const float4*)(Bp1 + kt + BK);
        }

        #pragma unroll
        for (int k = 0; k < BK; ++k) {
            float a[8], b[8];
            // A-fragment: rows ty*8..+7 (broadcast across tx lanes, N=1)
            #pragma unroll
            for (int i = 0; i < 8; ++i) a[i] = As[cur][k][ty*8 + i];
            // B-fragment: 4 cols @ tx*4, 4 cols @ 64+tx*4 (conflict-free)
            #pragma unroll
            for (int j = 0; j < 4; ++j) b[j]     = Bs[cur][k][tx*4 + j];
            #pragma unroll
            for (int j = 0; j < 4; ++j) b[4 + j] = Bs[cur][k][64 + tx*4 + j];
            #pragma unroll
            for (int i = 0; i < 8; ++i)
                #pragma unroll
                for (int j = 0; j < 8; ++j)
                    acc[i][j] = fmaf(a[i], b[j], acc[i][j]);
        }

        if (more) {
            const int nxt = cur ^ 1;
            As[nxt][lc+0][lr]    = pa0.x; As[nxt][lc+1][lr]    = pa0.y; As[nxt][lc+2][lr]    = pa0.z; As[nxt][lc+3][lr]    = pa0.w;
            Bs[nxt][lc+0][lr]    = pb0.x; Bs[nxt][lc+1][lr]    = pb0.y; Bs[nxt][lc+2][lr]    = pb0.z; Bs[nxt][lc+3][lr]    = pb0.w;
            As[nxt][lc+0][lr+64] = pa1.x; As[nxt][lc+1][lr+64] = pa1.y; As[nxt][lc+2][lr+64] = pa1.z; As[nxt][lc+3][lr+64] = pa1.w;
            Bs[nxt][lc+0][lr+64] = pb1.x; Bs[nxt][lc+1][lr+64] = pb1.y; Bs[nxt][lc+2][lr+64] = pb1.z; Bs[nxt][lc+3][lr+64] = pb1.w;
            __syncthreads();
        }
    }

    // Epilogue: bias (+GELU), two float4 stores per row at the split columns.
    const int colA = bn + tx*4;
    const int colB = bn + 64 + tx*4;
    float4 bv0 = *(const float4*)(bias + colA);
    float4 bv1 = *(const float4*)(bias + colB);

    #pragma unroll
    for (int i = 0; i < 8; ++i) {
        const int row = bm + ty*8 + i;
        float4 v0, v1;
        v0.x = acc[i][0] + bv0.x; v0.y = acc[i][1] + bv0.y;
        v0.z = acc[i][2] + bv0.z; v0.w = acc[i][3] + bv0.w;
        v1.x = acc[i][4] + bv1.x; v1.y = acc[i][5] + bv1.y;
        v1.z = acc[i][6] + bv1.z; v1.w = acc[i][7] + bv1.w;
        if (GELU) {
            v0.x = gelu_exact(v0.x); v0.y = gelu_exact(v0.y);
            v0.z = gelu_exact(v0.z); v0.w = gelu_exact(v0.w);
            v1.x = gelu_exact(v1.x); v1.y = gelu_exact(v1.y);
            v1.z = gelu_exact(v1.z); v1.w = gelu_exact(v1.w);
        }
        float* Crow = C + (size_t)row * N;
        *(float4*)(Crow + colA) = v0;
        *(float4*)(Crow + colB) = v1;
    }
}

// ---------------------------------------------------------------------------
// Codebook squared norms: cn[k] = sum_c E[k,c]^2. One block per code row.
// ---------------------------------------------------------------------------
__global__ void cb_norms(const float* __restrict__ E, float* __restrict__ cn)
{
    __shared__ float red[128];
    const int r = blockIdx.x;
    const float4 v = ((const float4*)(E + (size_t)r * C_DIM))[threadIdx.x];
    red[threadIdx.x] = v.x*v.x + v.y*v.y + v.z*v.z + v.w*v.w;
    __syncthreads();
    for (int o = 64; o > 0; o >>= 1) {
        if (threadIdx.x < o) red[threadIdx.x] += red[threadIdx.x + o];
        __syncthreads();
    }
    if (threadIdx.x == 0) cn[r] = red[0];
}

// ---------------------------------------------------------------------------
// Fused distance + argmin. For each token row: argmin_k (cn[k] - 2*x.e_k)
// (the per-token ||x||^2 constant does not affect argmin).
// Block: 64 tokens, loops all 1024 codes in tiles of 64, K=512 in tiles of 32.
// Tie-break: first (lowest) code index, matching jnp.argmin.
// (b-fragment already at tx*4 -> conflict-free.)
// ---------------------------------------------------------------------------
__global__ __launch_bounds__(256)
void dist_argmin(const float* __restrict__ X, const float* __restrict__ E,
                 const float* __restrict__ cn, int* __restrict__ outIdx)
{
    __shared__ float Xs[32][68];
    __shared__ float Es[32][68];
    __shared__ float sval[64][17];
    __shared__ int   sidx[64][17];

    const int bm = blockIdx.x * 64;
    const int tid = threadIdx.x;
    const int tx = tid & 15;        // 4 codes each
    const int ty = tid >> 4;        // 4 rows each
    const int lr = tid >> 3;        // 0..31
    const int lc = (tid & 7) << 2;  // 0..28

    float mval[4]; int midx[4];
    #pragma unroll
    for (int i = 0; i < 4; ++i) { mval[i] = INFINITY; midx[i] = 0; }

    for (int ct = 0; ct < K_CB; ct += 64) {
        float acc[4][4];
        #pragma unroll
        for (int i = 0; i < 4; ++i)
            #pragma unroll
            for (int j = 0; j < 4; ++j) acc[i][j] = 0.f;

        for (int kt = 0; kt < C_DIM; kt += 32) {
            float4 x0 = *(const float4*)(X + (size_t)(bm + lr)      * C_DIM + kt + lc);
            float4 x1 = *(const float4*)(X + (size_t)(bm + lr + 32) * C_DIM + kt + lc);
            float4 e0 = *(const float4*)(E + (size_t)(ct + lr)      * C_DIM + kt + lc);
            float4 e1 = *(const float4*)(E + (size_t)(ct + lr + 32) * C_DIM + kt + lc);
            __syncthreads();   // previous tile fully consumed
            Xs[lc+0][lr]    = x0.x; Xs[lc+1][lr]    = x0.y; Xs[lc+2][lr]    = x0.z; Xs[lc+3][lr]    = x0.w;
            Xs[lc+0][lr+32] = x1.x; Xs[lc+1][lr+32] = x1.y; Xs[lc+2][lr+32] = x1.z; Xs[lc+3][lr+32] = x1.w;
            Es[lc+0][lr]    = e0.x; Es[lc+1][lr]    = e0.y; Es[lc+2][lr]    = e0.z; Es[lc+3][lr]    = e0.w;
            Es[lc+0][lr+32] = e1.x; Es[lc+1][lr+32] = e1.y; Es[lc+2][lr+32] = e1.z; Es[lc+3][lr+32] = e1.w;
            __syncthreads();
            #pragma unroll
            for (int k = 0; k < 32; ++k) {
                float a[4], b[4];
                #pragma unroll
                for (int i = 0; i < 4; ++i) a[i] = Xs[k][ty*4 + i];
                #pragma unroll
                for (int j = 0; j < 4; ++j) b[j] = Es[k][tx*4 + j];
                #pragma unroll
                for (int i = 0; i < 4; ++i)
                    #pragma unroll
                    for (int j = 0; j < 4; ++j)
                        acc[i][j] = fmaf(a[i], b[j], acc[i][j]);
            }
        }

        #pragma unroll
        for (int j = 0; j < 4; ++j) {
            const int code = ct + tx*4 + j;
            const float cnj = cn[code];
            #pragma unroll
            for (int i = 0; i < 4; ++i) {
                const float d = fmaf(-2.0f, acc[i][j], cnj);
                // within a thread, code index is strictly increasing, so
                // strict < keeps the earliest index on exact ties.
                if (d < mval[i]) { mval[i] = d; midx[i] = code; }
            }
        }
    }

    __syncthreads();
    #pragma unroll
    for (int i = 0; i < 4; ++i) {
        sval[ty*4 + i][tx] = mval[i];
        sidx[ty*4 + i][tx] = midx[i];
    }
    __syncthreads();
    if (tid < 64) {
        float bv = sval[tid][0]; int bi = sidx[tid][0];
        #pragma unroll
        for (int t = 1; t < 16; ++t) {
            const float v = sval[tid][t]; const int ii = sidx[tid][t];
            if (v < bv || (v == bv && ii < bi)) { bv = v; bi = ii; }
        }
        outIdx[bm + tid] = bi;
    }
}

// ---------------------------------------------------------------------------
// Gather quantized = codebook[idx], write indices as float, and per-token
// commitment partial sum (compressed - quantized)^2. One block per token.
// ---------------------------------------------------------------------------
__global__ void gather_quant(const float* __restrict__ comp,
                             const float* __restrict__ E,
                             const int* __restrict__ idx,
                             float* __restrict__ quant,
                             float* __restrict__ outIdxF,
                             float* __restrict__ commTok)
{
    __shared__ float red[128];
    const int t = blockIdx.x;
    const int k = idx[t];
    const float4 ev = ((const float4*)(E    + (size_t)k * C_DIM))[threadIdx.x];
    const float4 cv = ((const float4*)(comp + (size_t)t * C_DIM))[threadIdx.x];
    ((float4*)(quant + (size_t)t * C_DIM))[threadIdx.x] = ev;
    const float dx = cv.x - ev.x, dy = cv.y - ev.y, dz = cv.z - ev.z, dw = cv.w - ev.w;
    red[threadIdx.x] = dx*dx + dy*dy + dz*dz + dw*dw;
    __syncthreads();
    for (int o = 64; o > 0; o >>= 1) {
        if (threadIdx.x < o) red[threadIdx.x] += red[threadIdx.x + o];
        __syncthreads();
    }
    if (threadIdx.x == 0) {
        commTok[t] = red[0];
        outIdxF[t] = (float)k;
    }
}

// ---------------------------------------------------------------------------
// Reconstruction loss partials (deterministic fixed-shape reduction).
// ---------------------------------------------------------------------------
__global__ void recon_partial(const float* __restrict__ R,
                              const float* __restrict__ S,
                              double* __restrict__ part)
{
    __shared__ double red[256];
    const size_t total = (size_t)M_TOK * D_DIM;
    double s = 0.0;
    for (size_t i = (size_t)blockIdx.x * blockDim.x + threadIdx.x; i < total;
         i += (size_t)gridDim.x * blockDim.x) {
        const float d = R[i] - S[i];
        s += (double)d * (double)d;
    }
    red[threadIdx.x] = s;
    __syncthreads();
    for (int o = 128; o > 0; o >>= 1) {
        if (threadIdx.x < o) red[threadIdx.x] += red[threadIdx.x + o];
        __syncthreads();
    }
    if (threadIdx.x == 0) part[blockIdx.x] = red[0];
}

__global__ void finalize_losses(const double* __restrict__ part,
                                const float* __restrict__ commTok,
                                float* __restrict__ outC,
                                float* __restrict__ outR)
{
    __shared__ double red[256];
    double s = 0.0;
    for (int i = threadIdx.x; i < 2048; i += 256) s += part[i];
    red[threadIdx.x] = s;
    __syncthreads();
    for (int o = 128; o > 0; o >>= 1) {
        if (threadIdx.x < o) red[threadIdx.x] += red[threadIdx.x + o];
        __syncthreads();
    }
    const double rsum = red[0];
    __syncthreads();

    double c = 0.0;
    for (int i = threadIdx.x; i < M_TOK; i += 256) c += (double)commTok[i];
    red[threadIdx.x] = c;
    __syncthreads();
    for (int o = 128; o > 0; o >>= 1) {
        if (threadIdx.x < o) red[threadIdx.x] += red[threadIdx.x + o];
        __syncthreads();
    }
    if (threadIdx.x == 0) {
        *outC = (float)(red[0] / (double)((size_t)M_TOK * C_DIM) * 0.25);
        *outR = (float)(rsum   / (double)((size_t)M_TOK * D_DIM));
    }
}

// ---------------------------------------------------------------------------
extern "C" void kernel_launch(void* const* d_in, const int* in_sizes, int n_in,
                              void* d_out, int out_size)
{
    const float* states   = (const float*)d_in[0];
    const float* We1      = (const float*)d_in[1];
    const float* be1      = (const float*)d_in[2];
    const float* We2      = (const float*)d_in[3];
    const float* be2      = (const float*)d_in[4];
    const float* Wd1      = (const float*)d_in[5];
    const float* bd1      = (const float*)d_in[6];
    const float* Wd2      = (const float*)d_in[7];
    const float* bd2      = (const float*)d_in[8];
    const float* codebook = (const float*)d_in[9];

    float* out = (float*)d_out;
    float* out_recon = out + OFF_RECON;
    float* out_comp  = out + OFF_COMP;
    float* out_quant = out + OFF_QUANT;
    float* out_idx   = out + OFF_IDX;
    float* out_closs = out + OFF_CLOSS;
    float* out_rloss = out + OFF_RLOSS;

    float  *hbuf, *cn, *commTok;
    int    *idx;
    double *part;
    cudaGetSymbolAddress((void**)&hbuf,    g_h);
    cudaGetSymbolAddress((void**)&cn,      g_cn);
    cudaGetSymbolAddress((void**)&idx,     g_idx);
    cudaGetSymbolAddress((void**)&commTok, g_comm_tok);
    cudaGetSymbolAddress((void**)&part,    g_partial);

    // codebook norms (independent, run first)
    cb_norms<<<K_CB, 128>>>(codebook, cn);

    // encoder: h = gelu(states @ We1^T + be1)   [16384 x 2048]
    gemm_nt_bias<true><<<dim3(H_DIM/128, M_TOK/128), 256>>>(
        states, We1, be1, hbuf, M_TOK, H_DIM, D_DIM);

    // compressed = h @ We2^T + be2              [16384 x 512]
    gemm_nt_bias<false><<<dim3(C_DIM/128, M_TOK/128), 256>>>(
        hbuf, We2, be2, out_comp, M_TOK, C_DIM, H_DIM);

    // nearest codebook entry per token
    dist_argmin<<<M_TOK/64, 256>>>(out_comp, codebook, cn, idx);

    // quantized + indices + commitment partials
    gather_quant<<<M_TOK, 128>>>(out_comp, codebook, idx, out_quant, out_idx, commTok);

    // decoder: h2 = gelu(quantized @ Wd1^T + bd1)   [16384 x 2048]
    gemm_nt_bias<true><<<dim3(H_DIM/128, M_TOK/128), 256>>>(
        out_quant, Wd1, bd1, hbuf, M_TOK, H_DIM, C_DIM);

    // reconstructed = h2 @ Wd2^T + bd2          [16384 x 4096]
    gemm_nt_bias<false><<<dim3(D_DIM/128, M_TOK/128), 256>>>(
        hbuf, Wd2, bd2, out_recon, M_TOK, D_DIM, H_DIM);

    // losses
    recon_partial<<<2048, 256>>>(out_recon, states, part);
    finalize_losses<<<1, 256>>>(part, commTok, out_closs, out_rloss);
}

// round 14
// speedup vs baseline: 1.1599x; 1.1599x over previous
#include <cuda_runtime.h>
#include <cuda_bf16.h>
#include <math.h>
#include <stdint.h>

// StateCompressor: VQ-VAE style encode -> quantize -> decode.
// Shapes: B=8,N=2048 -> M=16384 tokens; D=4096, H=2048, C=512, K=1024 codes.
//
// Output layout (float32, concatenated in reference-return order):
//   reconstructed [16384*4096] | compressed [16384*512] | quantized [16384*512]
//   | indices-as-float [16384] | commitment_loss [1] | reconstruction_loss [1]
//
// Round 13 (R5 resubmit; broker timeouts): decoder on bf16 tensor cores
// (mma.sync m16n8k16) with a 3-term precision split: x = hi + lo (bf16);
// x*y ~= hi*hi + lo*hi + hi*lo as ONE bf16 GEMM over K' = 3K with
// A' = [hi|lo|hi], B' = [hi|hi|lo]. Dropped lo*lo -> ~1e-5 rel err on
// reconstructed (tolerance 1e-3). Encoder + distance/argmin stay fp32:
// indices dominate the output norm, so ONE flipped index ~= 5e-3 rel err.

#define M_TOK 16384
#define D_DIM 4096
#define H_DIM 2048
#define C_DIM 512
#define K_CB  1024

#define OFF_RECON 0ull
#define OFF_COMP  67108864ull
#define OFF_QUANT 75497472ull
#define OFF_IDX   83886080ull
#define OFF_CLOSS 83902464ull
#define OFF_RLOSS 83902465ull

__device__ __align__(16) float g_h[(size_t)M_TOK * H_DIM];   // fp32 encoder scratch
__device__ float  g_cn[K_CB];
__device__ int    g_idx[M_TOK];
__device__ float  g_comm_tok[M_TOK];
__device__ double g_partial[2048];

// bf16 split buffers for the decoder tensor path
__device__ __align__(16) __nv_bfloat16 g_a2q[(size_t)M_TOK * (3*C_DIM)];   // quantized split [hi|lo|hi]
__device__ __align__(16) __nv_bfloat16 g_a2h[(size_t)M_TOK * (3*H_DIM)];   // h2 split        [hi|lo|hi]
__device__ __align__(16) __nv_bfloat16 g_w1s[(size_t)H_DIM * (3*C_DIM)];   // Wd1 split       [hi|hi|lo]
__device__ __align__(16) __nv_bfloat16 g_w2s[(size_t)D_DIM * (3*H_DIM)];   // Wd2 split       [hi|hi|lo]

__device__ __forceinline__ float gelu_exact(float v)
{
    return 0.5f * v * (1.0f + erff(v * 0.70710678118654752f));
}

__device__ __forceinline__ void mma_bf16(float* d, const uint32_t* a, const uint32_t* b)
{
    asm volatile(
        "mma.sync.aligned.m16n8k16.row.col.f32.bf16.bf16.f32 "
        "{%0,%1,%2,%3}, {%4,%5,%6,%7}, {%8,%9}, {%0,%1,%2,%3};\n"
        : "+f"(d[0]), "+f"(d[1]), "+f"(d[2]), "+f"(d[3])
        : "r"(a[0]), "r"(a[1]), "r"(a[2]), "r"(a[3]), "r"(b[0]), "r"(b[1]));
}

// ---------------------------------------------------------------------------
// fp32 SIMT NT GEMM (encoder only). 128x128 tile, BK=16, double-buffered,
// conflict-free split 4+4 B-fragment. Requires M%128==N%128==0, K%32==0.
// ---------------------------------------------------------------------------
template<bool GELU>
__global__ __launch_bounds__(256)
void gemm_nt_bias(const float* __restrict__ A, const float* __restrict__ B,
                  const float* __restrict__ bias, float* __restrict__ C,
                  int M, int N, int K)
{
    const int BK = 16;
    __shared__ float As[2][16][132];
    __shared__ float Bs[2][16][132];

    const int bm = blockIdx.y * 128;
    const int bn = blockIdx.x * 128;
    const int tid = threadIdx.x;
    const int tx = tid & 15;
    const int ty = tid >> 4;
    const int lr = tid >> 2;
    const int lc = (tid & 3) << 2;

    const float* Ap0 = A + (size_t)(bm + lr)      * K + lc;
    const float* Ap1 = A + (size_t)(bm + lr + 64) * K + lc;
    const float* Bp0 = B + (size_t)(bn + lr)      * K + lc;
    const float* Bp1 = B + (size_t)(bn + lr + 64) * K + lc;

    float acc[8][8];
    #pragma unroll
    for (int i = 0; i < 8; ++i)
        #pragma unroll
        for (int j = 0; j < 8; ++j) acc[i][j] = 0.f;

    {
        float4 pa0 = *(const float4*)(Ap0);
        float4 pb0 = *(const float4*)(Bp0);
        float4 pa1 = *(const float4*)(Ap1);
        float4 pb1 = *(const float4*)(Bp1);
        As[0][lc+0][lr]    = pa0.x; As[0][lc+1][lr]    = pa0.y; As[0][lc+2][lr]    = pa0.z; As[0][lc+3][lr]    = pa0.w;
        Bs[0][lc+0][lr]    = pb0.x; Bs[0][lc+1][lr]    = pb0.y; Bs[0][lc+2][lr]    = pb0.z; Bs[0][lc+3][lr]    = pb0.w;
        As[0][lc+0][lr+64] = pa1.x; As[0][lc+1][lr+64] = pa1.y; As[0][lc+2][lr+64] = pa1.z; As[0][lc+3][lr+64] = pa1.w;
        Bs[0][lc+0][lr+64] = pb1.x; Bs[0][lc+1][lr+64] = pb1.y; Bs[0][lc+2][lr+64] = pb1.z; Bs[0][lc+3][lr+64] = pb1.w;
    }
    __syncthreads();

    for (int kt = 0; kt < K; kt += BK) {
        const int cur = (kt >> 4) & 1;
        const bool more = (kt + BK) < K;

        float4 pa0, pa1, pb0, pb1;
        if (more) {
            pa0 = *(const float4*)(Ap0 + kt + BK);
            pb0 = *(const float4*)(Bp0 + kt + BK);
            pa1 = *(const float4*)(Ap1 + kt + BK);
            pb1 = *(const float4*)(Bp1 + kt + BK);
        }

        #pragma unroll
        for (int k = 0; k < BK; ++k) {
            float a[8], b[8];
            #pragma unroll
            for (int i = 0; i < 8; ++i) a[i] = As[cur][k][ty*8 + i];
            #pragma unroll
            for (int j = 0; j < 4; ++j) b[j]     = Bs[cur][k][tx*4 + j];
            #pragma unroll
            for (int j = 0; j < 4; ++j) b[4 + j] = Bs[cur][k][64 + tx*4 + j];
            #pragma unroll
            for (int i = 0; i < 8; ++i)
                #pragma unroll
                for (int j = 0; j < 8; ++j)
                    acc[i][j] = fmaf(a[i], b[j], acc[i][j]);
        }

        if (more) {
            const int nxt = cur ^ 1;
            As[nxt][lc+0][lr]    = pa0.x; As[nxt][lc+1][lr]    = pa0.y; As[nxt][lc+2][lr]    = pa0.z; As[nxt][lc+3][lr]    = pa0.w;
            Bs[nxt][lc+0][lr]    = pb0.x; Bs[nxt][lc+1][lr]    = pb0.y; Bs[nxt][lc+2][lr]    = pb0.z; Bs[nxt][lc+3][lr]    = pb0.w;
            As[nxt][lc+0][lr+64] = pa1.x; As[nxt][lc+1][lr+64] = pa1.y; As[nxt][lc+2][lr+64] = pa1.z; As[nxt][lc+3][lr+64] = pa1.w;
            Bs[nxt][lc+0][lr+64] = pb1.x; Bs[nxt][lc+1][lr+64] = pb1.y; Bs[nxt][lc+2][lr+64] = pb1.z; Bs[nxt][lc+3][lr+64] = pb1.w;
            __syncthreads();
        }
    }

    const int colA = bn + tx*4;
    const int colB = bn + 64 + tx*4;
    float4 bv0 = *(const float4*)(bias + colA);
    float4 bv1 = *(const float4*)(bias + colB);

    #pragma unroll
    for (int i = 0; i < 8; ++i) {
        const int row = bm + ty*8 + i;
        float4 v0, v1;
        v0.x = acc[i][0] + bv0.x; v0.y = acc[i][1] + bv0.y;
        v0.z = acc[i][2] + bv0.z; v0.w = acc[i][3] + bv0.w;
        v1.x = acc[i][4] + bv1.x; v1.y = acc[i][5] + bv1.y;
        v1.z = acc[i][6] + bv1.z; v1.w = acc[i][7] + bv1.w;
        if (GELU) {
            v0.x = gelu_exact(v0.x); v0.y = gelu_exact(v0.y);
            v0.z = gelu_exact(v0.z); v0.w = gelu_exact(v0.w);
            v1.x = gelu_exact(v1.x); v1.y = gelu_exact(v1.y);
            v1.z = gelu_exact(v1.z); v1.w = gelu_exact(v1.w);
        }
        float* Crow = C + (size_t)row * N;
        *(float4*)(Crow + colA) = v0;
        *(float4*)(Crow + colB) = v1;
    }
}

// ---------------------------------------------------------------------------
// bf16 tensor GEMM (decoder): C[m,n] = sum_k A[m,k]*B[n,k] + bias[n].
// A: MxK2 bf16 row-major (3-term split), B: NxK2 bf16 row-major.
// CTA 128x128, 8 warps (2x4), warp tile 64x32, m16n8k16 HMMA, BK=32,
// double-buffered smem with 40-element (80B) row stride -> conflict-free
// LDS for all fragment loads (bank = 20g+t mod 32: min nonzero 20*dg mod 32
// is 4 > dt <= 3).
// EPI=0: fp32 out + bias. EPI=1: gelu(out+bias) split to [hi|lo|hi] bf16
// buffer with row stride 3*N (feeds the next split GEMM as A).
// ---------------------------------------------------------------------------
template<int EPI>
__global__ __launch_bounds__(256)
void gemm_bf16_nt(const __nv_bfloat16* __restrict__ A,
                  const __nv_bfloat16* __restrict__ B,
                  const float* __restrict__ bias, void* __restrict__ Cout,
                  int M, int N, int K2)
{
    __shared__ __align__(16) __nv_bfloat16 As[2][128][40];
    __shared__ __align__(16) __nv_bfloat16 Bs[2][128][40];

    const int tid  = threadIdx.x;
    const int warp = tid >> 5;
    const int lane = tid & 31;
    const int g = lane >> 2;
    const int t = lane & 3;
    const int wm = warp >> 2;        // 0..1 (64-row halves)
    const int wn = warp & 3;         // 0..3 (32-col quarters)
    const int bm = blockIdx.y * 128;
    const int bn = blockIdx.x * 128;

    const int lrow = tid >> 1;          // 0..127
    const int lcol = (tid & 1) << 4;    // 0 or 16

    const __nv_bfloat16* Ag = A + (size_t)(bm + lrow) * K2 + lcol;
    const __nv_bfloat16* Bg = B + (size_t)(bn + lrow) * K2 + lcol;

    float acc[4][4][4];
    #pragma unroll
    for (int mi = 0; mi < 4; ++mi)
        #pragma unroll
        for (int ni = 0; ni < 4; ++ni)
            #pragma unroll
            for (int r = 0; r < 4; ++r) acc[mi][ni][r] = 0.f;

    // preload tile 0
    {
        uint4 a0 = *(const uint4*)(Ag);
        uint4 a1 = *(const uint4*)(Ag + 8);
        uint4 b0 = *(const uint4*)(Bg);
        uint4 b1 = *(const uint4*)(Bg + 8);
        *(uint4*)&As[0][lrow][lcol]     = a0;
        *(uint4*)&As[0][lrow][lcol + 8] = a1;
        *(uint4*)&Bs[0][lrow][lcol]     = b0;
        *(uint4*)&Bs[0][lrow][lcol + 8] = b1;
    }
    __syncthreads();

    for (int kt = 0; kt < K2; kt += 32) {
        const int cur = (kt >> 5) & 1;
        const bool more = (kt + 32) < K2;

        uint4 pa0, pa1, pb0, pb1;
        if (more) {
            pa0 = *(const uint4*)(Ag + kt + 32);
            pa1 = *(const uint4*)(Ag + kt + 40);
            pb0 = *(const uint4*)(Bg + kt + 32);
            pb1 = *(const uint4*)(Bg + kt + 40);
        }

        #pragma unroll
        for (int ks = 0; ks < 2; ++ks) {
            const int k0 = ks * 16;
            uint32_t af[4][4];
            uint32_t bf[4][2];
            #pragma unroll
            for (int mi = 0; mi < 4; ++mi) {
                const int r0 = wm*64 + mi*16;
                af[mi][0] = *(const uint32_t*)&As[cur][r0 + g    ][k0 + 2*t];
                af[mi][1] = *(const uint32_t*)&As[cur][r0 + g + 8][k0 + 2*t];
                af[mi][2] = *(const uint32_t*)&As[cur][r0 + g    ][k0 + 2*t + 8];
                af[mi][3] = *(const uint32_t*)&As[cur][r0 + g + 8][k0 + 2*t + 8];
            }
            #pragma unroll
            for (int ni = 0; ni < 4; ++ni) {
                const int c0 = wn*32 + ni*8;
                bf[ni][0] = *(const uint32_t*)&Bs[cur][c0 + g][k0 + 2*t];
                bf[ni][1] = *(const uint32_t*)&Bs[cur][c0 + g][k0 + 2*t + 8];
            }
            #pragma unroll
            for (int mi = 0; mi < 4; ++mi)
                #pragma unroll
                for (int ni = 0; ni < 4; ++ni)
                    mma_bf16(acc[mi][ni], af[mi], bf[ni]);
        }

        if (more) {
            const int nxt = cur ^ 1;
            *(uint4*)&As[nxt][lrow][lcol]     = pa0;
            *(uint4*)&As[nxt][lrow][lcol + 8] = pa1;
            *(uint4*)&Bs[nxt][lrow][lcol]     = pb0;
            *(uint4*)&Bs[nxt][lrow][lcol + 8] = pb1;
            __syncthreads();
        }
    }

    // Epilogue. D-frag mapping: d0=C[g][2t], d1=C[g][2t+1], d2=C[g+8][2t], d3=C[g+8][2t+1].
    #pragma unroll
    for (int ni = 0; ni < 4; ++ni) {
        const int c = bn + wn*32 + ni*8 + 2*t;
        const float2 bv = *(const float2*)(bias + c);
        #pragma unroll
        for (int mi = 0; mi < 4; ++mi) {
            const int r = bm + wm*64 + mi*16 + g;
            float v00 = acc[mi][ni][0] + bv.x;
            float v01 = acc[mi][ni][1] + bv.y;
            float v10 = acc[mi][ni][2] + bv.x;
            float v11 = acc[mi][ni][3] + bv.y;
            if (EPI == 0) {
                float* C = (float*)Cout;
                float2 p0; p0.x = v00; p0.y = v01;
                float2 p1; p1.x = v10; p1.y = v11;
                *(float2*)(C + (size_t)r       * N + c) = p0;
                *(float2*)(C + (size_t)(r + 8) * N + c) = p1;
            } else {
                // gelu, then split to [hi|lo|hi] rows of stride 3*N
                __nv_bfloat16* Dst = (__nv_bfloat16*)Cout;
                v00 = gelu_exact(v00); v01 = gelu_exact(v01);
                v10 = gelu_exact(v10); v11 = gelu_exact(v11);
                __nv_bfloat16 h00 = __float2bfloat16(v00);
                __nv_bfloat16 h01 = __float2bfloat16(v01);
                __nv_bfloat16 h10 = __float2bfloat16(v10);
                __nv_bfloat16 h11 = __float2bfloat16(v11);
                __nv_bfloat16 l00 = __float2bfloat16(v00 - __bfloat162float(h00));
                __nv_bfloat16 l01 = __float2bfloat16(v01 - __bfloat162float(h01));
                __nv_bfloat16 l10 = __float2bfloat16(v10 - __bfloat162float(h10));
                __nv_bfloat16 l11 = __float2bfloat16(v11 - __bfloat162float(h11));
                __nv_bfloat162 hp0; hp0.x = h00; hp0.y = h01;
                __nv_bfloat162 lp0; lp0.x = l00; lp0.y = l01;
                __nv_bfloat162 hp1; hp1.x = h10; hp1.y = h11;
                __nv_bfloat162 lp1; lp1.x = l10; lp1.y = l11;
                __nv_bfloat16* row0 = Dst + (size_t)r       * (3*N);
                __nv_bfloat16* row1 = Dst + (size_t)(r + 8) * (3*N);
                *(__nv_bfloat162*)(row0 + c)         = hp0;
                *(__nv_bfloat162*)(row0 + N + c)     = lp0;
                *(__nv_bfloat162*)(row0 + 2*N + c)   = hp0;
                *(__nv_bfloat162*)(row1 + c)         = hp1;
                *(__nv_bfloat162*)(row1 + N + c)     = lp1;
                *(__nv_bfloat162*)(row1 + 2*N + c)   = hp1;
            }
        }
    }
}

// ---------------------------------------------------------------------------
// Weight split: W [Nr x K] fp32 -> Wb [Nr x 3K] bf16 as [hi|hi|lo].
// ---------------------------------------------------------------------------
__global__ void split_w(const float* __restrict__ W, __nv_bfloat16* __restrict__ Wb,
                        int Nr, int K)
{
    const int i = blockIdx.x * 256 + threadIdx.x;
    if (i >= Nr * K) return;
    const int n = i / K, k = i % K;
    const float v = W[i];
    const __nv_bfloat16 hi = __float2bfloat16(v);
    const __nv_bfloat16 lo = __float2bfloat16(v - __bfloat162float(hi));
    __nv_bfloat16* row = Wb + (size_t)n * (3*K);
    row[k]       = hi;
    row[K + k]   = hi;
    row[2*K + k] = lo;
}

// ---------------------------------------------------------------------------
// Codebook squared norms.
// ---------------------------------------------------------------------------
__global__ void cb_norms(const float* __restrict__ E, float* __restrict__ cn)
{
    __shared__ float red[128];
    const int r = blockIdx.x;
    const float4 v = ((const float4*)(E + (size_t)r * C_DIM))[threadIdx.x];
    red[threadIdx.x] = v.x*v.x + v.y*v.y + v.z*v.z + v.w*v.w;
    __syncthreads();
    for (int o = 64; o > 0; o >>= 1) {
        if (threadIdx.x < o) red[threadIdx.x] += red[threadIdx.x + o];
        __syncthreads();
    }
    if (threadIdx.x == 0) cn[r] = red[0];
}

// ---------------------------------------------------------------------------
// Fused distance + argmin (fp32, unchanged from the R4 pass).
// ---------------------------------------------------------------------------
__global__ __launch_bounds__(256)
void dist_argmin(const float* __restrict__ X, const float* __restrict__ E,
                 const float* __restrict__ cn, int* __restrict__ outIdx)
{
    __shared__ float Xs[32][68];
    __shared__ float Es[32][68];
    __shared__ float sval[64][17];
    __shared__ int   sidx[64][17];

    const int bm = blockIdx.x * 64;
    const int tid = threadIdx.x;
    const int tx = tid & 15;
    const int ty = tid >> 4;
    const int lr = tid >> 3;
    const int lc = (tid & 7) << 2;

    float mval[4]; int midx[4];
    #pragma unroll
    for (int i = 0; i < 4; ++i) { mval[i] = INFINITY; midx[i] = 0; }

    for (int ct = 0; ct < K_CB; ct += 64) {
        float acc[4][4];
        #pragma unroll
        for (int i = 0; i < 4; ++i)
            #pragma unroll
            for (int j = 0; j < 4; ++j) acc[i][j] = 0.f;

        for (int kt = 0; kt < C_DIM; kt += 32) {
            float4 x0 = *(const float4*)(X + (size_t)(bm + lr)      * C_DIM + kt + lc);
            float4 x1 = *(const float4*)(X + (size_t)(bm + lr + 32) * C_DIM + kt + lc);
            float4 e0 = *(const float4*)(E + (size_t)(ct + lr)      * C_DIM + kt + lc);
            float4 e1 = *(const float4*)(E + (size_t)(ct + lr + 32) * C_DIM + kt + lc);
            __syncthreads();
            Xs[lc+0][lr]    = x0.x; Xs[lc+1][lr]    = x0.y; Xs[lc+2][lr]    = x0.z; Xs[lc+3][lr]    = x0.w;
            Xs[lc+0][lr+32] = x1.x; Xs[lc+1][lr+32] = x1.y; Xs[lc+2][lr+32] = x1.z; Xs[lc+3][lr+32] = x1.w;
            Es[lc+0][lr]    = e0.x; Es[lc+1][lr]    = e0.y; Es[lc+2][lr]    = e0.z; Es[lc+3][lr]    = e0.w;
            Es[lc+0][lr+32] = e1.x; Es[lc+1][lr+32] = e1.y; Es[lc+2][lr+32] = e1.z; Es[lc+3][lr+32] = e1.w;
            __syncthreads();
            #pragma unroll
            for (int k = 0; k < 32; ++k) {
                float a[4], b[4];
                #pragma unroll
                for (int i = 0; i < 4; ++i) a[i] = Xs[k][ty*4 + i];
                #pragma unroll
                for (int j = 0; j < 4; ++j) b[j] = Es[k][tx*4 + j];
                #pragma unroll
                for (int i = 0; i < 4; ++i)
                    #pragma unroll
                    for (int j = 0; j < 4; ++j)
                        acc[i][j] = fmaf(a[i], b[j], acc[i][j]);
            }
        }

        #pragma unroll
        for (int j = 0; j < 4; ++j) {
            const int code = ct + tx*4 + j;
            const float cnj = cn[code];
            #pragma unroll
            for (int i = 0; i < 4; ++i) {
                const float d = fmaf(-2.0f, acc[i][j], cnj);
                if (d < mval[i]) { mval[i] = d; midx[i] = code; }
            }
        }
    }

    __syncthreads();
    #pragma unroll
    for (int i = 0; i < 4; ++i) {
        sval[ty*4 + i][tx] = mval[i];
        sidx[ty*4 + i][tx] = midx[i];
    }
    __syncthreads();
    if (tid < 64) {
        float bv = sval[tid][0]; int bi = sidx[tid][0];
        #pragma unroll
        for (int t = 1; t < 16; ++t) {
            const float v = sval[tid][t]; const int ii = sidx[tid][t];
            if (v < bv || (v == bv && ii < bi)) { bv = v; bi = ii; }
        }
        outIdx[bm + tid] = bi;
    }
}

// ---------------------------------------------------------------------------
// Gather: quantized (fp32 out), indices-as-float, commitment partials, and
// the bf16 split of quantized ([hi|lo|hi]) for the decoder tensor GEMM.
// ---------------------------------------------------------------------------
__global__ void gather_quant(const float* __restrict__ comp,
                             const float* __restrict__ E,
                             const int* __restrict__ idx,
                             float* __restrict__ quant,
                             float* __restrict__ outIdxF,
                             float* __restrict__ commTok,
                             __nv_bfloat16* __restrict__ a2q)
{
    __shared__ float red[128];
    const int t = blockIdx.x;
    const int k = idx[t];
    const float4 ev = ((const float4*)(E    + (size_t)k * C_DIM))[threadIdx.x];
    const float4 cv = ((const float4*)(comp + (size_t)t * C_DIM))[threadIdx.x];
    ((float4*)(quant + (size_t)t * C_DIM))[threadIdx.x] = ev;

    // bf16 split of the 4 quantized values
    {
        const int c = threadIdx.x * 4;
        __nv_bfloat16* row = a2q + (size_t)t * (3*C_DIM);
        const float vv[4] = {ev.x, ev.y, ev.z, ev.w};
        __nv_bfloat16 hi[4], lo[4];
        #pragma unroll
        for (int j = 0; j < 4; ++j) {
            hi[j] = __float2bfloat16(vv[j]);
            lo[j] = __float2bfloat16(vv[j] - __bfloat162float(hi[j]));
        }
        __nv_bfloat162 hp0; hp0.x = hi[0]; hp0.y = hi[1];
        __nv_bfloat162 hp1; hp1.x = hi[2]; hp1.y = hi[3];
        __nv_bfloat162 lp0; lp0.x = lo[0]; lp0.y = lo[1];
        __nv_bfloat162 lp1; lp1.x = lo[2]; lp1.y = lo[3];
        *(__nv_bfloat162*)(row + c)                = hp0;
        *(__nv_bfloat162*)(row + c + 2)            = hp1;
        *(__nv_bfloat162*)(row + C_DIM + c)        = lp0;
        *(__nv_bfloat162*)(row + C_DIM + c + 2)    = lp1;
        *(__nv_bfloat162*)(row + 2*C_DIM + c)      = hp0;
        *(__nv_bfloat162*)(row + 2*C_DIM + c + 2)  = hp1;
    }

    const float dx = cv.x - ev.x, dy = cv.y - ev.y, dz = cv.z - ev.z, dw = cv.w - ev.w;
    red[threadIdx.x] = dx*dx + dy*dy + dz*dz + dw*dw;
    __syncthreads();
    for (int o = 64; o > 0; o >>= 1) {
        if (threadIdx.x < o) red[threadIdx.x] += red[threadIdx.x + o];
        __syncthreads();
    }
    if (threadIdx.x == 0) {
        commTok[t] = red[0];
        outIdxF[t] = (float)k;
    }
}

// ---------------------------------------------------------------------------
// Loss reductions (deterministic, unchanged).
// ---------------------------------------------------------------------------
__global__ void recon_partial(const float* __restrict__ R,
                              const float* __restrict__ S,
                              double* __restrict__ part)
{
    __shared__ double red[256];
    const size_t total = (size_t)M_TOK * D_DIM;
    double s = 0.0;
    for (size_t i = (size_t)blockIdx.x * blockDim.x + threadIdx.x; i < total;
         i += (size_t)gridDim.x * blockDim.x) {
        const float d = R[i] - S[i];
        s += (double)d * (double)d;
    }
    red[threadIdx.x] = s;
    __syncthreads();
    for (int o = 128; o > 0; o >>= 1) {
        if (threadIdx.x < o) red[threadIdx.x] += red[threadIdx.x + o];
        __syncthreads();
    }
    if (threadIdx.x == 0) part[blockIdx.x] = red[0];
}

__global__ void finalize_losses(const double* __restrict__ part,
                                const float* __restrict__ commTok,
                                float* __restrict__ outC,
                                float* __restrict__ outR)
{
    __shared__ double red[256];
    double s = 0.0;
    for (int i = threadIdx.x; i < 2048; i += 256) s += part[i];
    red[threadIdx.x] = s;
    __syncthreads();
    for (int o = 128; o > 0; o >>= 1) {
        if (threadIdx.x < o) red[threadIdx.x] += red[threadIdx.x + o];
        __syncthreads();
    }
    const double rsum = red[0];
    __syncthreads();

    double c = 0.0;
    for (int i = threadIdx.x; i < M_TOK; i += 256) c += (double)commTok[i];
    red[threadIdx.x] = c;
    __syncthreads();
    for (int o = 128; o > 0; o >>= 1) {
        if (threadIdx.x < o) red[threadIdx.x] += red[threadIdx.x + o];
        __syncthreads();
    }
    if (threadIdx.x == 0) {
        *outC = (float)(red[0] / (double)((size_t)M_TOK * C_DIM) * 0.25);
        *outR = (float)(rsum   / (double)((size_t)M_TOK * D_DIM));
    }
}

// ---------------------------------------------------------------------------
extern "C" void kernel_launch(void* const* d_in, const int* in_sizes, int n_in,
                              void* d_out, int out_size)
{
    const float* states   = (const float*)d_in[0];
    const float* We1      = (const float*)d_in[1];
    const float* be1      = (const float*)d_in[2];
    const float* We2      = (const float*)d_in[3];
    const float* be2      = (const float*)d_in[4];
    const float* Wd1      = (const float*)d_in[5];
    const float* bd1      = (const float*)d_in[6];
    const float* Wd2      = (const float*)d_in[7];
    const float* bd2      = (const float*)d_in[8];
    const float* codebook = (const float*)d_in[9];

    float* out = (float*)d_out;
    float* out_recon = out + OFF_RECON;
    float* out_comp  = out + OFF_COMP;
    float* out_quant = out + OFF_QUANT;
    float* out_idx   = out + OFF_IDX;
    float* out_closs = out + OFF_CLOSS;
    float* out_rloss = out + OFF_RLOSS;

    float  *hbuf, *cn, *commTok;
    int    *idx;
    double *part;
    __nv_bfloat16 *a2q, *a2h, *w1s, *w2s;
    cudaGetSymbolAddress((void**)&hbuf,    g_h);
    cudaGetSymbolAddress((void**)&cn,      g_cn);
    cudaGetSymbolAddress((void**)&idx,     g_idx);
    cudaGetSymbolAddress((void**)&commTok, g_comm_tok);
    cudaGetSymbolAddress((void**)&part,    g_partial);
    cudaGetSymbolAddress((void**)&a2q,     g_a2q);
    cudaGetSymbolAddress((void**)&a2h,     g_a2h);
    cudaGetSymbolAddress((void**)&w1s,     g_w1s);
    cudaGetSymbolAddress((void**)&w2s,     g_w2s);

    // independent prep
    cb_norms<<<K_CB, 128>>>(codebook, cn);
    split_w<<<(H_DIM*C_DIM + 255)/256, 256>>>(Wd1, w1s, H_DIM, C_DIM);
    split_w<<<(D_DIM*H_DIM + 255)/256, 256>>>(Wd2, w2s, D_DIM, H_DIM);

    // encoder (fp32 SIMT): h = gelu(states @ We1^T + be1)   [16384 x 2048]
    gemm_nt_bias<true><<<dim3(H_DIM/128, M_TOK/128), 256>>>(
        states, We1, be1, hbuf, M_TOK, H_DIM, D_DIM);

    // compressed = h @ We2^T + be2              [16384 x 512]
    gemm_nt_bias<false><<<dim3(C_DIM/128, M_TOK/128), 256>>>(
        hbuf, We2, be2, out_comp, M_TOK, C_DIM, H_DIM);

    // nearest codebook entry per token (fp32)
    dist_argmin<<<M_TOK/64, 256>>>(out_comp, codebook, cn, idx);

    // quantized + indices + commitment partials + bf16 split of quantized
    gather_quant<<<M_TOK, 128>>>(out_comp, codebook, idx, out_quant, out_idx,
                                 commTok, a2q);

    // decoder (bf16 tensor, 3-term split):
    // h2 = gelu(quantized @ Wd1^T + bd1), emitted directly as split bf16
    gemm_bf16_nt<1><<<dim3(H_DIM/128, M_TOK/128), 256>>>(
        a2q, w1s, bd1, a2h, M_TOK, H_DIM, 3*C_DIM);

    // reconstructed = h2 @ Wd2^T + bd2          [16384 x 4096] fp32 out
    gemm_bf16_nt<0><<<dim3(D_DIM/128, M_TOK/128), 256>>>(
        a2h, w2s, bd2, out_recon, M_TOK, D_DIM, 3*H_DIM);

    // losses
    recon_partial<<<2048, 256>>>(out_recon, states, part);
    finalize_losses<<<1, 256>>>(part, commTok, out_closs, out_rloss);
}

// round 17
// speedup vs baseline: 1.2351x; 1.0648x over previous
#include <cuda_runtime.h>
#include <cuda_bf16.h>
#include <math.h>
#include <stdint.h>

// StateCompressor: VQ-VAE style encode -> quantize -> decode.
// Shapes: B=8,N=2048 -> M=16384 tokens; D=4096, H=2048, C=512, K=1024 codes.
//
// Output layout (float32, concatenated in reference-return order):
//   reconstructed [16384*4096] | compressed [16384*512] | quantized [16384*512]
//   | indices-as-float [16384] | commitment_loss [1] | reconstruction_loss [1]
//
// Round 16 (R15 resubmit; broker timeout): decoder split storage reduced
// from [hi|lo|hi] (3K) to [hi|lo] (2K). The GEMM loops logical K, loads 4
// tiles per 16-chunk (Ahi,Alo,Bhi,Blo) and runs 3 fragment passes (hi*hi,
// hi*lo, lo*hi) reusing hi fragments in registers: same HMMA count, -33%
// global traffic, -33% LDS. Math identical to R14 (rel_err 1.47e-5
// measured, tol 1e-3). Encoder + distance/argmin stay fp32: one flipped
// index ~= 5e-3 rel err.

#define M_TOK 16384
#define D_DIM 4096
#define H_DIM 2048
#define C_DIM 512
#define K_CB  1024

#define OFF_RECON 0ull
#define OFF_COMP  67108864ull
#define OFF_QUANT 75497472ull
#define OFF_IDX   83886080ull
#define OFF_CLOSS 83902464ull
#define OFF_RLOSS 83902465ull

__device__ __align__(16) float g_h[(size_t)M_TOK * H_DIM];   // fp32 encoder scratch
__device__ float  g_cn[K_CB];
__device__ int    g_idx[M_TOK];
__device__ float  g_comm_tok[M_TOK];
__device__ double g_partial[2048];

// bf16 [hi|lo] split buffers for the decoder tensor path (row stride 2*K)
__device__ __align__(16) __nv_bfloat16 g_a2q[(size_t)M_TOK * (2*C_DIM)];   // quantized split
__device__ __align__(16) __nv_bfloat16 g_a2h[(size_t)M_TOK * (2*H_DIM)];   // h2 split
__device__ __align__(16) __nv_bfloat16 g_w1s[(size_t)H_DIM * (2*C_DIM)];   // Wd1 split
__device__ __align__(16) __nv_bfloat16 g_w2s[(size_t)D_DIM * (2*H_DIM)];   // Wd2 split

__device__ __forceinline__ float gelu_exact(float v)
{
    return 0.5f * v * (1.0f + erff(v * 0.70710678118654752f));
}

__device__ __forceinline__ void mma_bf16(float* d, const uint32_t* a, const uint32_t* b)
{
    asm volatile(
        "mma.sync.aligned.m16n8k16.row.col.f32.bf16.bf16.f32 "
        "{%0,%1,%2,%3}, {%4,%5,%6,%7}, {%8,%9}, {%0,%1,%2,%3};\n"
        : "+f"(d[0]), "+f"(d[1]), "+f"(d[2]), "+f"(d[3])
        : "r"(a[0]), "r"(a[1]), "r"(a[2]), "r"(a[3]), "r"(b[0]), "r"(b[1]));
}

// ---------------------------------------------------------------------------
// fp32 SIMT NT GEMM (encoder only). Unchanged from the R14 pass.
// ---------------------------------------------------------------------------
template<bool GELU>
__global__ __launch_bounds__(256)
void gemm_nt_bias(const float* __restrict__ A, const float* __restrict__ B,
                  const float* __restrict__ bias, float* __restrict__ C,
                  int M, int N, int K)
{
    const int BK = 16;
    __shared__ float As[2][16][132];
    __shared__ float Bs[2][16][132];

    const int bm = blockIdx.y * 128;
    const int bn = blockIdx.x * 128;
    const int tid = threadIdx.x;
    const int tx = tid & 15;
    const int ty = tid >> 4;
    const int lr = tid >> 2;
    const int lc = (tid & 3) << 2;

    const float* Ap0 = A + (size_t)(bm + lr)      * K + lc;
    const float* Ap1 = A + (size_t)(bm + lr + 64) * K + lc;
    const float* Bp0 = B + (size_t)(bn + lr)      * K + lc;
    const float* Bp1 = B + (size_t)(bn + lr + 64) * K + lc;

    float acc[8][8];
    #pragma unroll
    for (int i = 0; i < 8; ++i)
        #pragma unroll
        for (int j = 0; j < 8; ++j) acc[i][j] = 0.f;

    {
        float4 pa0 = *(const float4*)(Ap0);
        float4 pb0 = *(const float4*)(Bp0);
        float4 pa1 = *(const float4*)(Ap1);
        float4 pb1 = *(const float4*)(Bp1);
        As[0][lc+0][lr]    = pa0.x; As[0][lc+1][lr]    = pa0.y; As[0][lc+2][lr]    = pa0.z; As[0][lc+3][lr]    = pa0.w;
        Bs[0][lc+0][lr]    = pb0.x; Bs[0][lc+1][lr]    = pb0.y; Bs[0][lc+2][lr]    = pb0.z; Bs[0][lc+3][lr]    = pb0.w;
        As[0][lc+0][lr+64] = pa1.x; As[0][lc+1][lr+64] = pa1.y; As[0][lc+2][lr+64] = pa1.z; As[0][lc+3][lr+64] = pa1.w;
        Bs[0][lc+0][lr+64] = pb1.x; Bs[0][lc+1][lr+64] = pb1.y; Bs[0][lc+2][lr+64] = pb1.z; Bs[0][lc+3][lr+64] = pb1.w;
    }
    __syncthreads();

    for (int kt = 0; kt < K; kt += BK) {
        const int cur = (kt >> 4) & 1;
        const bool more = (kt + BK) < K;

        float4 pa0, pa1, pb0, pb1;
        if (more) {
            pa0 = *(const float4*)(Ap0 + kt + BK);
            pb0 = *(const float4*)(Bp0 + kt + BK);
            pa1 = *(const float4*)(Ap1 + kt + BK);
            pb1 = *(const float4*)(Bp1 + kt + BK);
        }

        #pragma unroll
        for (int k = 0; k < BK; ++k) {
            float a[8], b[8];
            #pragma unroll
            for (int i = 0; i < 8; ++i) a[i] = As[cur][k][ty*8 + i];
            #pragma unroll
            for (int j = 0; j < 4; ++j) b[j]     = Bs[cur][k][tx*4 + j];
            #pragma unroll
            for (int j = 0; j < 4; ++j) b[4 + j] = Bs[cur][k][64 + tx*4 + j];
            #pragma unroll
            for (int i = 0; i < 8; ++i)
                #pragma unroll
                for (int j = 0; j < 8; ++j)
                    acc[i][j] = fmaf(a[i], b[j], acc[i][j]);
        }

        if (more) {
            const int nxt = cur ^ 1;
            As[nxt][lc+0][lr]    = pa0.x; As[nxt][lc+1][lr]    = pa0.y; As[nxt][lc+2][lr]    = pa0.z; As[nxt][lc+3][lr]    = pa0.w;
            Bs[nxt][lc+0][lr]    = pb0.x; Bs[nxt][lc+1][lr]    = pb0.y; Bs[nxt][lc+2][lr]    = pb0.z; Bs[nxt][lc+3][lr]    = pb0.w;
            As[nxt][lc+0][lr+64] = pa1.x; As[nxt][lc+1][lr+64] = pa1.y; As[nxt][lc+2][lr+64] = pa1.z; As[nxt][lc+3][lr+64] = pa1.w;
            Bs[nxt][lc+0][lr+64] = pb1.x; Bs[nxt][lc+1][lr+64] = pb1.y; Bs[nxt][lc+2][lr+64] = pb1.z; Bs[nxt][lc+3][lr+64] = pb1.w;
            __syncthreads();
        }
    }

    const int colA = bn + tx*4;
    const int colB = bn + 64 + tx*4;
    float4 bv0 = *(const float4*)(bias + colA);
    float4 bv1 = *(const float4*)(bias + colB);

    #pragma unroll
    for (int i = 0; i < 8; ++i) {
        const int row = bm + ty*8 + i;
        float4 v0, v1;
        v0.x = acc[i][0] + bv0.x; v0.y = acc[i][1] + bv0.y;
        v0.z = acc[i][2] + bv0.z; v0.w = acc[i][3] + bv0.w;
        v1.x = acc[i][4] + bv1.x; v1.y = acc[i][5] + bv1.y;
        v1.z = acc[i][6] + bv1.z; v1.w = acc[i][7] + bv1.w;
        if (GELU) {
            v0.x = gelu_exact(v0.x); v0.y = gelu_exact(v0.y);
            v0.z = gelu_exact(v0.z); v0.w = gelu_exact(v0.w);
            v1.x = gelu_exact(v1.x); v1.y = gelu_exact(v1.y);
            v1.z = gelu_exact(v1.z); v1.w = gelu_exact(v1.w);
        }
        float* Crow = C + (size_t)row * N;
        *(float4*)(Crow + colA) = v0;
        *(float4*)(Crow + colB) = v1;
    }
}

// ---------------------------------------------------------------------------
// bf16 tensor GEMM v2 (decoder): C[m,n] = sum_k (Ahi+Alo)[m,k]*(Bhi+Blo)[n,k]
// ~= sum_k Ahi*Bhi + Ahi*Blo + Alo*Bhi   (lo*lo dropped, ~1.5e-5 rel err).
// A: M x 2K bf16 [hi(0..K) | lo(K..2K)]. B: N x 2K likewise. Loops logical K
// in 16-chunks; per chunk loads 4 tiles (Ahi,Alo,Bhi,Blo; 128x16 each, pad
// to 24 -> fragment banks 12g+t mod 32 all distinct, conflict-free) and runs
// 3 fragment passes reusing hi fragments in registers. 48 HMMA + 48 LDS.32
// per warp per chunk. smem 4 x [2][128][24] bf16 = 48KB static (limit).
// EPI=0: fp32 out + bias. EPI=1: gelu(out+bias) -> [hi|lo] rows, stride 2N.
// ---------------------------------------------------------------------------
template<int EPI>
__global__ __launch_bounds__(256)
void gemm_bf16_nt2(const __nv_bfloat16* __restrict__ A,
                   const __nv_bfloat16* __restrict__ B,
                   const float* __restrict__ bias, void* __restrict__ Cout,
                   int M, int N, int K)
{
    __shared__ __align__(16) __nv_bfloat16 Ah[2][128][24];
    __shared__ __align__(16) __nv_bfloat16 Al[2][128][24];
    __shared__ __align__(16) __nv_bfloat16 Bh[2][128][24];
    __shared__ __align__(16) __nv_bfloat16 Bl[2][128][24];

    const int tid  = threadIdx.x;
    const int warp = tid >> 5;
    const int lane = tid & 31;
    const int g = lane >> 2;
    const int t = lane & 3;
    const int wm = warp >> 2;        // 0..1 (64-row halves)
    const int wn = warp & 3;         // 0..3 (32-col quarters)
    const int bm = blockIdx.y * 128;
    const int bn = blockIdx.x * 128;

    const int lrow = tid >> 1;          // 0..127
    const int lcol = (tid & 1) << 3;    // 0 or 8 elements (uint4 = 8 bf16)

    const __nv_bfloat16* Agh = A + (size_t)(bm + lrow) * (2*K) + lcol;
    const __nv_bfloat16* Agl = Agh + K;
    const __nv_bfloat16* Bgh = B + (size_t)(bn + lrow) * (2*K) + lcol;
    const __nv_bfloat16* Bgl = Bgh + K;

    float acc[4][4][4];
    #pragma unroll
    for (int mi = 0; mi < 4; ++mi)
        #pragma unroll
        for (int ni = 0; ni < 4; ++ni)
            #pragma unroll
            for (int r = 0; r < 4; ++r) acc[mi][ni][r] = 0.f;

    // preload chunk 0
    {
        *(uint4*)&Ah[0][lrow][lcol] = *(const uint4*)(Agh);
        *(uint4*)&Al[0][lrow][lcol] = *(const uint4*)(Agl);
        *(uint4*)&Bh[0][lrow][lcol] = *(const uint4*)(Bgh);
        *(uint4*)&Bl[0][lrow][lcol] = *(const uint4*)(Bgl);
    }
    __syncthreads();

    for (int kt = 0; kt < K; kt += 16) {
        const int cur = (kt >> 4) & 1;
        const bool more = (kt + 16) < K;

        uint4 pah, pal, pbh, pbl;
        if (more) {
            pah = *(const uint4*)(Agh + kt + 16);
            pal = *(const uint4*)(Agl + kt + 16);
            pbh = *(const uint4*)(Bgh + kt + 16);
            pbl = *(const uint4*)(Bgl + kt + 16);
        }

        uint32_t af_hi[4][4], af_lo[4][4];
        uint32_t bf_hi[4][2], bf_lo[4][2];

        // Pass 1: hi * hi
        #pragma unroll
        for (int mi = 0; mi < 4; ++mi) {
            const int r0 = wm*64 + mi*16;
            af_hi[mi][0] = *(const uint32_t*)&Ah[cur][r0 + g    ][2*t];
            af_hi[mi][1] = *(const uint32_t*)&Ah[cur][r0 + g + 8][2*t];
            af_hi[mi][2] = *(const uint32_t*)&Ah[cur][r0 + g    ][2*t + 8];
            af_hi[mi][3] = *(const uint32_t*)&Ah[cur][r0 + g + 8][2*t + 8];
        }
        #pragma unroll
        for (int ni = 0; ni < 4; ++ni) {
            const int c0 = wn*32 + ni*8;
            bf_hi[ni][0] = *(const uint32_t*)&Bh[cur][c0 + g][2*t];
            bf_hi[ni][1] = *(const uint32_t*)&Bh[cur][c0 + g][2*t + 8];
        }
        #pragma unroll
        for (int mi = 0; mi < 4; ++mi)
            #pragma unroll
            for (int ni = 0; ni < 4; ++ni)
                mma_bf16(acc[mi][ni], af_hi[mi], bf_hi[ni]);

        // Pass 2: hi * lo (reuse af_hi)
        #pragma unroll
        for (int ni = 0; ni < 4; ++ni) {
            const int c0 = wn*32 + ni*8;
            bf_lo[ni][0] = *(const uint32_t*)&Bl[cur][c0 + g][2*t];
            bf_lo[ni][1] = *(const uint32_t*)&Bl[cur][c0 + g][2*t + 8];
        }
        #pragma unroll
        for (int mi = 0; mi < 4; ++mi)
            #pragma unroll
            for (int ni = 0; ni < 4; ++ni)
                mma_bf16(acc[mi][ni], af_hi[mi], bf_lo[ni]);

        // Pass 3: lo * hi (reuse bf_hi)
        #pragma unroll
        for (int mi = 0; mi < 4; ++mi) {
            const int r0 = wm*64 + mi*16;
            af_lo[mi][0] = *(const uint32_t*)&Al[cur][r0 + g    ][2*t];
            af_lo[mi][1] = *(const uint32_t*)&Al[cur][r0 + g + 8][2*t];
            af_lo[mi][2] = *(const uint32_t*)&Al[cur][r0 + g    ][2*t + 8];
            af_lo[mi][3] = *(const uint32_t*)&Al[cur][r0 + g + 8][2*t + 8];
        }
        #pragma unroll
        for (int mi = 0; mi < 4; ++mi)
            #pragma unroll
            for (int ni = 0; ni < 4; ++ni)
                mma_bf16(acc[mi][ni], af_lo[mi], bf_hi[ni]);

        if (more) {
            const int nxt = cur ^ 1;
            *(uint4*)&Ah[nxt][lrow][lcol] = pah;
            *(uint4*)&Al[nxt][lrow][lcol] = pal;
            *(uint4*)&Bh[nxt][lrow][lcol] = pbh;
            *(uint4*)&Bl[nxt][lrow][lcol] = pbl;
            __syncthreads();
        }
    }

    // Epilogue. D-frag mapping: d0=C[g][2t], d1=C[g][2t+1], d2=C[g+8][2t], d3=C[g+8][2t+1].
    #pragma unroll
    for (int ni = 0; ni < 4; ++ni) {
        const int c = bn + wn*32 + ni*8 + 2*t;
        const float2 bv = *(const float2*)(bias + c);
        #pragma unroll
        for (int mi = 0; mi < 4; ++mi) {
            const int r = bm + wm*64 + mi*16 + g;
            float v00 = acc[mi][ni][0] + bv.x;
            float v01 = acc[mi][ni][1] + bv.y;
            float v10 = acc[mi][ni][2] + bv.x;
            float v11 = acc[mi][ni][3] + bv.y;
            if (EPI == 0) {
                float* C = (float*)Cout;
                float2 p0; p0.x = v00; p0.y = v01;
                float2 p1; p1.x = v10; p1.y = v11;
                *(float2*)(C + (size_t)r       * N + c) = p0;
                *(float2*)(C + (size_t)(r + 8) * N + c) = p1;
            } else {
                // gelu, then split to [hi|lo] rows of stride 2*N
                __nv_bfloat16* Dst = (__nv_bfloat16*)Cout;
                v00 = gelu_exact(v00); v01 = gelu_exact(v01);
                v10 = gelu_exact(v10); v11 = gelu_exact(v11);
                __nv_bfloat16 h00 = __float2bfloat16(v00);
                __nv_bfloat16 h01 = __float2bfloat16(v01);
                __nv_bfloat16 h10 = __float2bfloat16(v10);
                __nv_bfloat16 h11 = __float2bfloat16(v11);
                __nv_bfloat16 l00 = __float2bfloat16(v00 - __bfloat162float(h00));
                __nv_bfloat16 l01 = __float2bfloat16(v01 - __bfloat162float(h01));
                __nv_bfloat16 l10 = __float2bfloat16(v10 - __bfloat162float(h10));
                __nv_bfloat16 l11 = __float2bfloat16(v11 - __bfloat162float(h11));
                __nv_bfloat162 hp0; hp0.x = h00; hp0.y = h01;
                __nv_bfloat162 lp0; lp0.x = l00; lp0.y = l01;
                __nv_bfloat162 hp1; hp1.x = h10; hp1.y = h11;
                __nv_bfloat162 lp1; lp1.x = l10; lp1.y = l11;
                __nv_bfloat16* row0 = Dst + (size_t)r       * (2*N);
                __nv_bfloat16* row1 = Dst + (size_t)(r + 8) * (2*N);
                *(__nv_bfloat162*)(row0 + c)       = hp0;
                *(__nv_bfloat162*)(row0 + N + c)   = lp0;
                *(__nv_bfloat162*)(row1 + c)       = hp1;
                *(__nv_bfloat162*)(row1 + N + c)   = lp1;
            }
        }
    }
}

// ---------------------------------------------------------------------------
// Weight split: W [Nr x K] fp32 -> Wb [Nr x 2K] bf16 as [hi|lo].
// ---------------------------------------------------------------------------
__global__ void split_w(const float* __restrict__ W, __nv_bfloat16* __restrict__ Wb,
                        int Nr, int K)
{
    const int i = blockIdx.x * 256 + threadIdx.x;
    if (i >= Nr * K) return;
    const int n = i / K, k = i % K;
    const float v = W[i];
    const __nv_bfloat16 hi = __float2bfloat16(v);
    const __nv_bfloat16 lo = __float2bfloat16(v - __bfloat162float(hi));
    __nv_bfloat16* row = Wb + (size_t)n * (2*K);
    row[k]     = hi;
    row[K + k] = lo;
}

// ---------------------------------------------------------------------------
// Codebook squared norms.
// ---------------------------------------------------------------------------
__global__ void cb_norms(const float* __restrict__ E, float* __restrict__ cn)
{
    __shared__ float red[128];
    const int r = blockIdx.x;
    const float4 v = ((const float4*)(E + (size_t)r * C_DIM))[threadIdx.x];
    red[threadIdx.x] = v.x*v.x + v.y*v.y + v.z*v.z + v.w*v.w;
    __syncthreads();
    for (int o = 64; o > 0; o >>= 1) {
        if (threadIdx.x < o) red[threadIdx.x] += red[threadIdx.x + o];
        __syncthreads();
    }
    if (threadIdx.x == 0) cn[r] = red[0];
}

// ---------------------------------------------------------------------------
// Fused distance + argmin (fp32, unchanged from the R14 pass).
// ---------------------------------------------------------------------------
__global__ __launch_bounds__(256)
void dist_argmin(const float* __restrict__ X, const float* __restrict__ E,
                 const float* __restrict__ cn, int* __restrict__ outIdx)
{
    __shared__ float Xs[32][68];
    __shared__ float Es[32][68];
    __shared__ float sval[64][17];
    __shared__ int   sidx[64][17];

    const int bm = blockIdx.x * 64;
    const int tid = threadIdx.x;
    const int tx = tid & 15;
    const int ty = tid >> 4;
    const int lr = tid >> 3;
    const int lc = (tid & 7) << 2;

    float mval[4]; int midx[4];
    #pragma unroll
    for (int i = 0; i < 4; ++i) { mval[i] = INFINITY; midx[i] = 0; }

    for (int ct = 0; ct < K_CB; ct += 64) {
        float acc[4][4];
        #pragma unroll
        for (int i = 0; i < 4; ++i)
            #pragma unroll
            for (int j = 0; j < 4; ++j) acc[i][j] = 0.f;

        for (int kt = 0; kt < C_DIM; kt += 32) {
            float4 x0 = *(const float4*)(X + (size_t)(bm + lr)      * C_DIM + kt + lc);
            float4 x1 = *(const float4*)(X + (size_t)(bm + lr + 32) * C_DIM + kt + lc);
            float4 e0 = *(const float4*)(E + (size_t)(ct + lr)      * C_DIM + kt + lc);
            float4 e1 = *(const float4*)(E + (size_t)(ct + lr + 32) * C_DIM + kt + lc);
            __syncthreads();
            Xs[lc+0][lr]    = x0.x; Xs[lc+1][lr]    = x0.y; Xs[lc+2][lr]    = x0.z; Xs[lc+3][lr]    = x0.w;
            Xs[lc+0][lr+32] = x1.x; Xs[lc+1][lr+32] = x1.y; Xs[lc+2][lr+32] = x1.z; Xs[lc+3][lr+32] = x1.w;
            Es[lc+0][lr]    = e0.x; Es[lc+1][lr]    = e0.y; Es[lc+2][lr]    = e0.z; Es[lc+3][lr]    = e0.w;
            Es[lc+0][lr+32] = e1.x; Es[lc+1][lr+32] = e1.y; Es[lc+2][lr+32] = e1.z; Es[lc+3][lr+32] = e1.w;
            __syncthreads();
            #pragma unroll
            for (int k = 0; k < 32; ++k) {
                float a[4], b[4];
                #pragma unroll
                for (int i = 0; i < 4; ++i) a[i] = Xs[k][ty*4 + i];
                #pragma unroll
                for (int j = 0; j < 4; ++j) b[j] = Es[k][tx*4 + j];
                #pragma unroll
                for (int i = 0; i < 4; ++i)
                    #pragma unroll
                    for (int j = 0; j < 4; ++j)
                        acc[i][j] = fmaf(a[i], b[j], acc[i][j]);
            }
        }

        #pragma unroll
        for (int j = 0; j < 4; ++j) {
            const int code = ct + tx*4 + j;
            const float cnj = cn[code];
            #pragma unroll
            for (int i = 0; i < 4; ++i) {
                const float d = fmaf(-2.0f, acc[i][j], cnj);
                if (d < mval[i]) { mval[i] = d; midx[i] = code; }
            }
        }
    }

    __syncthreads();
    #pragma unroll
    for (int i = 0; i < 4; ++i) {
        sval[ty*4 + i][tx] = mval[i];
        sidx[ty*4 + i][tx] = midx[i];
    }
    __syncthreads();
    if (tid < 64) {
        float bv = sval[tid][0]; int bi = sidx[tid][0];
        #pragma unroll
        for (int t = 1; t < 16; ++t) {
            const float v = sval[tid][t]; const int ii = sidx[tid][t];
            if (v < bv || (v == bv && ii < bi)) { bv = v; bi = ii; }
        }
        outIdx[bm + tid] = bi;
    }
}

// ---------------------------------------------------------------------------
// Gather: quantized (fp32 out), indices-as-float, commitment partials, and
// the bf16 [hi|lo] split of quantized for the decoder tensor GEMM.
// ---------------------------------------------------------------------------
__global__ void gather_quant(const float* __restrict__ comp,
                             const float* __restrict__ E,
                             const int* __restrict__ idx,
                             float* __restrict__ quant,
                             float* __restrict__ outIdxF,
                             float* __restrict__ commTok,
                             __nv_bfloat16* __restrict__ a2q)
{
    __shared__ float red[128];
    const int t = blockIdx.x;
    const int k = idx[t];
    const float4 ev = ((const float4*)(E    + (size_t)k * C_DIM))[threadIdx.x];
    const float4 cv = ((const float4*)(comp + (size_t)t * C_DIM))[threadIdx.x];
    ((float4*)(quant + (size_t)t * C_DIM))[threadIdx.x] = ev;

    // bf16 [hi|lo] split of the 4 quantized values
    {
        const int c = threadIdx.x * 4;
        __nv_bfloat16* row = a2q + (size_t)t * (2*C_DIM);
        const float vv[4] = {ev.x, ev.y, ev.z, ev.w};
        __nv_bfloat16 hi[4], lo[4];
        #pragma unroll
        for (int j = 0; j < 4; ++j) {
            hi[j] = __float2bfloat16(vv[j]);
            lo[j] = __float2bfloat16(vv[j] - __bfloat162float(hi[j]));
        }
        __nv_bfloat162 hp0; hp0.x = hi[0]; hp0.y = hi[1];
        __nv_bfloat162 hp1; hp1.x = hi[2]; hp1.y = hi[3];
        __nv_bfloat162 lp0; lp0.x = lo[0]; lp0.y = lo[1];
        __nv_bfloat162 lp1; lp1.x = lo[2]; lp1.y = lo[3];
        *(__nv_bfloat162*)(row + c)               = hp0;
        *(__nv_bfloat162*)(row + c + 2)           = hp1;
        *(__nv_bfloat162*)(row + C_DIM + c)       = lp0;
        *(__nv_bfloat162*)(row + C_DIM + c + 2)   = lp1;
    }

    const float dx = cv.x - ev.x, dy = cv.y - ev.y, dz = cv.z - ev.z, dw = cv.w - ev.w;
    red[threadIdx.x] = dx*dx + dy*dy + dz*dz + dw*dw;
    __syncthreads();
    for (int o = 64; o > 0; o >>= 1) {
        if (threadIdx.x < o) red[threadIdx.x] += red[threadIdx.x + o];
        __syncthreads();
    }
    if (threadIdx.x == 0) {
        commTok[t] = red[0];
        outIdxF[t] = (float)k;
    }
}

// ---------------------------------------------------------------------------
// Loss reductions (deterministic, unchanged).
// ---------------------------------------------------------------------------
__global__ void recon_partial(const float* __restrict__ R,
                              const float* __restrict__ S,
                              double* __restrict__ part)
{
    __shared__ double red[256];
    const size_t total = (size_t)M_TOK * D_DIM;
    double s = 0.0;
    for (size_t i = (size_t)blockIdx.x * blockDim.x + threadIdx.x; i < total;
         i += (size_t)gridDim.x * blockDim.x) {
        const float d = R[i] - S[i];
        s += (double)d * (double)d;
    }
    red[threadIdx.x] = s;
    __syncthreads();
    for (int o = 128; o > 0; o >>= 1) {
        if (threadIdx.x < o) red[threadIdx.x] += red[threadIdx.x + o];
        __syncthreads();
    }
    if (threadIdx.x == 0) part[blockIdx.x] = red[0];
}

__global__ void finalize_losses(const double* __restrict__ part,
                                const float* __restrict__ commTok,
                                float* __restrict__ outC,
                                float* __restrict__ outR)
{
    __shared__ double red[256];
    double s = 0.0;
    for (int i = threadIdx.x; i < 2048; i += 256) s += part[i];
    red[threadIdx.x] = s;
    __syncthreads();
    for (int o = 128; o > 0; o >>= 1) {
        if (threadIdx.x < o) red[threadIdx.x] += red[threadIdx.x + o];
        __syncthreads();
    }
    const double rsum = red[0];
    __syncthreads();

    double c = 0.0;
    for (int i = threadIdx.x; i < M_TOK; i += 256) c += (double)commTok[i];
    red[threadIdx.x] = c;
    __syncthreads();
    for (int o = 128; o > 0; o >>= 1) {
        if (threadIdx.x < o) red[threadIdx.x] += red[threadIdx.x + o];
        __syncthreads();
    }
    if (threadIdx.x == 0) {
        *outC = (float)(red[0] / (double)((size_t)M_TOK * C_DIM) * 0.25);
        *outR = (float)(rsum   / (double)((size_t)M_TOK * D_DIM));
    }
}

// ---------------------------------------------------------------------------
extern "C" void kernel_launch(void* const* d_in, const int* in_sizes, int n_in,
                              void* d_out, int out_size)
{
    const float* states   = (const float*)d_in[0];
    const float* We1      = (const float*)d_in[1];
    const float* be1      = (const float*)d_in[2];
    const float* We2      = (const float*)d_in[3];
    const float* be2      = (const float*)d_in[4];
    const float* Wd1      = (const float*)d_in[5];
    const float* bd1      = (const float*)d_in[6];
    const float* Wd2      = (const float*)d_in[7];
    const float* bd2      = (const float*)d_in[8];
    const float* codebook = (const float*)d_in[9];

    float* out = (float*)d_out;
    float* out_recon = out + OFF_RECON;
    float* out_comp  = out + OFF_COMP;
    float* out_quant = out + OFF_QUANT;
    float* out_idx   = out + OFF_IDX;
    float* out_closs = out + OFF_CLOSS;
    float* out_rloss = out + OFF_RLOSS;

    float  *hbuf, *cn, *commTok;
    int    *idx;
    double *part;
    __nv_bfloat16 *a2q, *a2h, *w1s, *w2s;
    cudaGetSymbolAddress((void**)&hbuf,    g_h);
    cudaGetSymbolAddress((void**)&cn,      g_cn);
    cudaGetSymbolAddress((void**)&idx,     g_idx);
    cudaGetSymbolAddress((void**)&commTok, g_comm_tok);
    cudaGetSymbolAddress((void**)&part,    g_partial);
    cudaGetSymbolAddress((void**)&a2q,     g_a2q);
    cudaGetSymbolAddress((void**)&a2h,     g_a2h);
    cudaGetSymbolAddress((void**)&w1s,     g_w1s);
    cudaGetSymbolAddress((void**)&w2s,     g_w2s);

    // independent prep
    cb_norms<<<K_CB, 128>>>(codebook, cn);
    split_w<<<(H_DIM*C_DIM + 255)/256, 256>>>(Wd1, w1s, H_DIM, C_DIM);
    split_w<<<(D_DIM*H_DIM + 255)/256, 256>>>(Wd2, w2s, D_DIM, H_DIM);

    // encoder (fp32 SIMT): h = gelu(states @ We1^T + be1)   [16384 x 2048]
    gemm_nt_bias<true><<<dim3(H_DIM/128, M_TOK/128), 256>>>(
        states, We1, be1, hbuf, M_TOK, H_DIM, D_DIM);

    // compressed = h @ We2^T + be2              [16384 x 512]
    gemm_nt_bias<false><<<dim3(C_DIM/128, M_TOK/128), 256>>>(
        hbuf, We2, be2, out_comp, M_TOK, C_DIM, H_DIM);

    // nearest codebook entry per token (fp32)
    dist_argmin<<<M_TOK/64, 256>>>(out_comp, codebook, cn, idx);

    // quantized + indices + commitment partials + [hi|lo] split of quantized
    gather_quant<<<M_TOK, 128>>>(out_comp, codebook, idx, out_quant, out_idx,
                                 commTok, a2q);

    // decoder (bf16 tensor, [hi|lo] 3-pass split):
    // h2 = gelu(quantized @ Wd1^T + bd1), emitted directly as [hi|lo] bf16
    gemm_bf16_nt2<1><<<dim3(H_DIM/128, M_TOK/128), 256>>>(
        a2q, w1s, bd1, a2h, M_TOK, H_DIM, C_DIM);

    // reconstructed = h2 @ Wd2^T + bd2          [16384 x 4096] fp32 out
    gemm_bf16_nt2<0><<<dim3(D_DIM/128, M_TOK/128), 256>>>(
        a2h, w2s, bd2, out_recon, M_TOK, D_DIM, H_DIM);

    // losses
    recon_partial<<<2048, 256>>>(out_recon, states, part);
    finalize_losses<<<1, 256>>>(part, commTok, out_closs, out_rloss);
}